// round 16
// baseline (speedup 1.0000x reference)
#include <cuda_runtime.h>
#include <cuda_fp16.h>
#include <math.h>
#include <stdint.h>

#define BATCH 8
#define NPTS  8192
#define MPTS  2048
#define C1    128
#define C2    256
#define CMID  256

// ---------------- scratch (device globals; no allocation allowed) ----------
__device__ int   g_idx[BATCH * NPTS * 3];
__device__ float g_w  [BATCH * NPTS * 3];
__device__ __align__(256) float g_kfT[BATCH * MPTS * C2];        // kf transposed [b][m][c]
__device__ __align__(256) __half g_B1 [BATCH * NPTS * 384];      // [b][n][384] fp16
__device__ __align__(256) __half g_B2 [BATCH * NPTS * 256];      // [b][n][256] fp16
__device__ __align__(256) __half g_W1s[256 * 384];               // [m][384] fp16
__device__ __align__(256) __half g_W2s[256 * 256];               // [m][256] fp16

// ---------------- helpers ----------------------------------------------------
__device__ __forceinline__ uint32_t smem_u32(const void* p) {
    uint32_t a;
    asm("{ .reg .u64 t; cvta.to.shared.u64 t, %1; cvt.u32.u64 %0, t; }" : "=r"(a) : "l"(p));
    return a;
}
#define CP_ASYNC16(dst, src) \
    asm volatile("cp.async.cg.shared.global [%0], [%1], 16;" :: "r"(dst), "l"(src))
#define CP_COMMIT() asm volatile("cp.async.commit_group;" ::: "memory")
#define CP_WAIT0()  asm volatile("cp.async.wait_group 0;" ::: "memory")
#define CP_WAIT1()  asm volatile("cp.async.wait_group 1;" ::: "memory")

#define LDSM4(r0, r1, r2, r3, addr) \
    asm volatile("ldmatrix.sync.aligned.m8n8.x4.shared.b16 {%0,%1,%2,%3}, [%4];" \
        : "=r"(r0), "=r"(r1), "=r"(r2), "=r"(r3) : "r"(addr))

#define MMAF16(d, a, b) \
    asm volatile("mma.sync.aligned.m16n8k16.row.col.f32.f16.f16.f32 " \
        "{%0,%1,%2,%3}, {%4,%5,%6,%7}, {%8,%9}, {%0,%1,%2,%3};" \
        : "+f"(d[0]), "+f"(d[1]), "+f"(d[2]), "+f"(d[3]) \
        : "r"(a[0]), "r"(a[1]), "r"(a[2]), "r"(a[3]), "r"(b[0]), "r"(b[1]))

__device__ __forceinline__ uint32_t pack_h2(float a, float b) {
    __half2 h = __floats2half2_rn(a, b);
    return *(uint32_t*)&h;
}

// ---------------- kernel 1: three_nn (1 pt/thread, t-space) ------------------
__global__ __launch_bounds__(256)
void three_nn_kernel(const float* __restrict__ unknown,
                     const float* __restrict__ known)
{
    __shared__ float4 sk[MPTS];
    const int b = blockIdx.y;
    const int j = blockIdx.x * blockDim.x + threadIdx.x;

    const float* kb = known + (size_t)b * MPTS * 3;
    for (int i = threadIdx.x; i < MPTS; i += blockDim.x) {
        float x = kb[i * 3 + 0], y = kb[i * 3 + 1], z = kb[i * 3 + 2];
        sk[i] = make_float4(x, y, z, x * x + y * y + z * z);
    }
    __syncthreads();

    const float* up = unknown + ((size_t)b * NPTS + j) * 3;
    const float ux = up[0], uy = up[1], uz = up[2];
    const float u2 = ux * ux + uy * uy + uz * uz;
    const float m2x = -2.0f * ux, m2y = -2.0f * uy, m2z = -2.0f * uz;

    float t0 = 3.4e38f, t1 = 3.4e38f, t2v = 3.4e38f;
    int i0 = 0, i1 = 0, i2 = 0;

    #pragma unroll 4
    for (int i = 0; i < MPTS; i++) {
        float4 k = sk[i];
        float t = fmaf(m2x, k.x, k.w);
        t = fmaf(m2y, k.y, t);
        t = fmaf(m2z, k.z, t);
        if (t < t2v) {
            if (t < t0)      { t2v = t1; i2 = i1; t1 = t0; i1 = i0; t0 = t; i0 = i; }
            else if (t < t1) { t2v = t1; i2 = i1; t1 = t;  i1 = i; }
            else             { t2v = t;  i2 = i; }
        }
    }

    float s0 = sqrtf(fmaxf(t0 + u2, 0.0f));
    float s1 = sqrtf(fmaxf(t1 + u2, 0.0f));
    float s2 = sqrtf(fmaxf(t2v + u2, 0.0f));
    float r0 = 1.0f / (s0 + 1e-8f);
    float r1 = 1.0f / (s1 + 1e-8f);
    float r2 = 1.0f / (s2 + 1e-8f);
    float rs = r0 + r1 + r2;

    const int o = ((b * NPTS) + j) * 3;
    g_idx[o + 0] = i0; g_idx[o + 1] = i1; g_idx[o + 2] = i2;
    g_w[o + 0] = r0 / rs; g_w[o + 1] = r1 / rs; g_w[o + 2] = r2 / rs;
}

// ---------------- kernel 2: transpose kf -> kfT [b][m][c] -------------------
__global__ __launch_bounds__(256)
void kf_transpose_kernel(const float* __restrict__ kf, float* __restrict__ kfT)
{
    __shared__ float s[32][33];
    const int b  = blockIdx.z;
    const int m0 = blockIdx.x * 32;
    const int c0 = blockIdx.y * 32;
    const int lane = threadIdx.x & 31, r = threadIdx.x >> 5;

    #pragma unroll
    for (int k = 0; k < 4; k++) {
        int c = r + k * 8;
        s[c][lane] = kf[((size_t)b * C2 + c0 + c) * MPTS + m0 + lane];
    }
    __syncthreads();
    #pragma unroll
    for (int k = 0; k < 4; k++) {
        int m = r + k * 8;
        kfT[((size_t)b * MPTS + m0 + m) * C2 + c0 + lane] = s[lane][m];
    }
}

// ---------------- kernel 3: fused interp + uf -> B1 full rows (fp16) --------
__global__ __launch_bounds__(256)
void interp_fused_kernel(const float* __restrict__ kfT,
                         const float* __restrict__ uf,
                         __half* __restrict__ B1)
{
    __shared__ float s[C1][33];
    const int b    = blockIdx.y;
    const int j0   = blockIdx.x * 32;
    const int lane = threadIdx.x & 31;
    const int warp = threadIdx.x >> 5;

    #pragma unroll
    for (int k = 0; k < 16; k++) {
        int c = warp + k * 8;
        s[c][lane] = uf[((size_t)b * C1 + c) * NPTS + j0 + lane];
    }
    __syncthreads();

    const int jbase = j0 + warp * 4;
    #pragma unroll
    for (int t = 0; t < 4; t++) {
        const int j = jbase + t;
        const int o = ((b * NPTS) + j) * 3;
        const int   i0 = g_idx[o + 0], i1 = g_idx[o + 1], i2 = g_idx[o + 2];
        const float w0 = g_w[o + 0],   w1 = g_w[o + 1],   w2 = g_w[o + 2];

        const float* r0 = kfT + ((size_t)b * MPTS + i0) * C2 + lane * 8;
        const float* r1 = kfT + ((size_t)b * MPTS + i1) * C2 + lane * 8;
        const float* r2 = kfT + ((size_t)b * MPTS + i2) * C2 + lane * 8;

        float4 a0 = *(const float4*)(r0);
        float4 a1 = *(const float4*)(r0 + 4);
        float4 b0 = *(const float4*)(r1);
        float4 b1 = *(const float4*)(r1 + 4);
        float4 c0 = *(const float4*)(r2);
        float4 c1 = *(const float4*)(r2 + 4);

        float v[8];
        v[0] = a0.x * w0 + b0.x * w1 + c0.x * w2;
        v[1] = a0.y * w0 + b0.y * w1 + c0.y * w2;
        v[2] = a0.z * w0 + b0.z * w1 + c0.z * w2;
        v[3] = a0.w * w0 + b0.w * w1 + c0.w * w2;
        v[4] = a1.x * w0 + b1.x * w1 + c1.x * w2;
        v[5] = a1.y * w0 + b1.y * w1 + c1.y * w2;
        v[6] = a1.z * w0 + b1.z * w1 + c1.z * w2;
        v[7] = a1.w * w0 + b1.w * w1 + c1.w * w2;

        uint4 hv;
        hv.x = pack_h2(v[0], v[1]); hv.y = pack_h2(v[2], v[3]);
        hv.z = pack_h2(v[4], v[5]); hv.w = pack_h2(v[6], v[7]);

        *(uint4*)(B1 + ((size_t)b * NPTS + j) * 384 + lane * 8) = hv;
    }

    #pragma unroll
    for (int t = 0; t < 4; t++) {
        int jl = warp * 4 + t;
        __half* row = B1 + ((size_t)b * NPTS + j0 + jl) * 384 + 256;
        int c = lane * 4;
        uint2 out;
        out.x = pack_h2(s[c + 0][jl], s[c + 1][jl]);
        out.y = pack_h2(s[c + 2][jl], s[c + 3][jl]);
        *(uint2*)(row + c) = out;
    }
}

// ---------------- weight convert (both layers, one launch, plain fp16) ------
__global__ __launch_bounds__(256)
void convert_w_kernel(const float* __restrict__ W1, __half* __restrict__ W1s,
                      const float* __restrict__ W2, __half* __restrict__ W2s)
{
    int idx = blockIdx.x * 256 + threadIdx.x;
    const int N1 = 256 * 384;
    if (idx < N1) {
        W1s[idx] = __float2half_rn(W1[idx]);
    } else {
        int i2 = idx - N1;
        if (i2 >= 256 * 256) return;
        W2s[i2] = __float2half_rn(W2[i2]);
    }
}

// ---------------- mma.sync GEMM (plain fp16) + fused epilogue ----------------
// A = Ws [256][K] fp16; B = [b][n][K] fp16.  C = A.B
// CTA 128x128, 4 warps (warp 64x64).
// K=64 per stage, 3-stage rotation -> ONE sync per stage.
// smem row = 128B data + 16B pad, pitch 144 (ldmatrix conflict-free).
#define PT 144
#define TILE_T 18432          // 128*144
#define STAGEB 36864          // A + B per stage
#define GSMEM  (3 * STAGEB)   // 110592

__global__ __launch_bounds__(128, 2)
void gemm_mma_kernel(const __half* __restrict__ Ws,
                     const float* __restrict__ bias,
                     const __half* __restrict__ Bmat,
                     float* __restrict__ Cout,
                     __half* __restrict__ B2out,
                     int Ksrc)
{
    extern __shared__ __align__(16) char smem[];
    const uint32_t sb = smem_u32(smem);

    const int tid  = threadIdx.x;
    const int wid  = tid >> 5;
    const int lane = tid & 31;
    const int wr   = wid >> 1;          // 0..1 (m half)
    const int wc   = wid & 1;           // 0..1 (n half)

    const int S  = Ksrc >> 6;           // 64-k stages

    const int b     = blockIdx.z;
    const int mBase = blockIdx.y * 128;
    const int nBase = blockIdx.x * 128;

    const __half* Abase = Ws + (size_t)mBase * Ksrc;
    const __half* Bbase = Bmat + ((size_t)b * NPTS + nBase) * Ksrc;

    float acc[4][8][4];
    #pragma unroll
    for (int i = 0; i < 4; i++)
        #pragma unroll
        for (int j = 0; j < 8; j++)
            #pragma unroll
            for (int q = 0; q < 4; q++) acc[i][j][q] = 0.0f;

    // load maps: each operand 128 rows x 8 chunks(16B); 1024 chunks, 8/thread
    #define LOAD_STAGE(sidx, buf) do {                                            \
        const int _s = (sidx);                                                    \
        const uint32_t _ab = sb + (buf) * STAGEB;                                 \
        const uint32_t _bb = _ab + TILE_T;                                        \
        _Pragma("unroll")                                                         \
        for (int _k = 0; _k < 8; _k++) {                                          \
            int _id = tid + _k * 128;                                             \
            int _r = _id >> 3, _q = _id & 7;                                      \
            CP_ASYNC16(_ab + _r * PT + _q * 16,                                   \
                       Abase + (size_t)_r * Ksrc + _s * 64 + _q * 8);             \
            CP_ASYNC16(_bb + _r * PT + _q * 16,                                   \
                       Bbase + (size_t)_r * Ksrc + _s * 64 + _q * 8);             \
        }                                                                         \
    } while (0)

    LOAD_STAGE(0, 0); CP_COMMIT();
    LOAD_STAGE(1, 1); CP_COMMIT();

    int buf = 0;
    for (int s = 0; s < S; s++) {
        if (s < S - 1) CP_WAIT1(); else CP_WAIT0();
        __syncthreads();
        if (s + 2 < S) {
            LOAD_STAGE(s + 2, (s + 2) % 3);
            CP_COMMIT();
        }

        const uint32_t aB = sb + buf * STAGEB;
        const uint32_t bB = aB + TILE_T;

        #pragma unroll
        for (int kk = 0; kk < 4; kk++) {
            uint32_t ah[4][4];
            #pragma unroll
            for (int i = 0; i < 4; i++) {
                int row = wr * 64 + i * 16 + (lane & 15);
                uint32_t addr = aB + row * PT + kk * 32 + (lane >> 4) * 16;
                LDSM4(ah[i][0], ah[i][1], ah[i][2], ah[i][3], addr);
            }
            #pragma unroll
            for (int jp = 0; jp < 4; jp++) {
                uint32_t bf[4];
                int row = wc * 64 + jp * 16 + (lane & 15);
                uint32_t addr = bB + row * PT + kk * 32 + (lane >> 4) * 16;
                LDSM4(bf[0], bf[1], bf[2], bf[3], addr);
                uint32_t b0[2] = { bf[0], bf[2] };
                uint32_t b1[2] = { bf[1], bf[3] };
                #pragma unroll
                for (int i = 0; i < 4; i++) {
                    MMAF16(acc[i][jp * 2 + 0], ah[i], b0);
                    MMAF16(acc[i][jp * 2 + 1], ah[i], b1);
                }
            }
        }
        buf = (buf + 1) % 3;
    }

    if (B2out) {
        // staged transpose: B2 [n][256] fp16 single plane
        __half* sm = (__half*)smem;          // [128 n][136 m]
        __syncthreads();                     // smem reuse guard (no loop-end sync)
        #pragma unroll
        for (int i = 0; i < 4; i++) {
            const int ml0 = wr * 64 + i * 16 + (lane >> 2);
            const float bv0 = bias[mBase + ml0];
            const float bv1 = bias[mBase + ml0 + 8];
            #pragma unroll
            for (int jn = 0; jn < 8; jn++) {
                const int nl = wc * 64 + jn * 8 + (lane & 3) * 2;
                #pragma unroll
                for (int q = 0; q < 4; q++) {
                    const int ml = ml0 + ((q >= 2) ? 8 : 0);
                    const int nn = nl + (q & 1);
                    const float v = fmaxf(acc[i][jn][q] + ((q >= 2) ? bv1 : bv0), 0.0f);
                    sm[nn * 136 + ml] = __float2half_rn(v);
                }
            }
        }
        __syncthreads();
        const __half* src = sm + tid * 136;
        __half* dstrow = B2out + ((size_t)b * NPTS + nBase + tid) * 256 + mBase;
        #pragma unroll
        for (int q = 0; q < 16; q++)
            *(uint4*)(dstrow + q * 8) = *(const uint4*)(src + q * 8);
    } else {
        float* Cb = Cout + (size_t)b * 256 * NPTS;
        #pragma unroll
        for (int i = 0; i < 4; i++) {
            const int r0 = mBase + wr * 64 + i * 16 + (lane >> 2);
            const float bv0 = bias[r0];
            const float bv1 = bias[r0 + 8];
            float* cr0 = Cb + (size_t)r0 * NPTS;
            float* cr1 = Cb + (size_t)(r0 + 8) * NPTS;
            #pragma unroll
            for (int jn = 0; jn < 8; jn++) {
                const int col = nBase + wc * 64 + jn * 8 + (lane & 3) * 2;
                float2 v0, v1;
                v0.x = fmaxf(acc[i][jn][0] + bv0, 0.0f);
                v0.y = fmaxf(acc[i][jn][1] + bv0, 0.0f);
                v1.x = fmaxf(acc[i][jn][2] + bv1, 0.0f);
                v1.y = fmaxf(acc[i][jn][3] + bv1, 0.0f);
                *(float2*)&cr0[col] = v0;
                *(float2*)&cr1[col] = v1;
            }
        }
    }
}

// ---------------- launch -----------------------------------------------------
extern "C" void kernel_launch(void* const* d_in, const int* in_sizes, int n_in,
                              void* d_out, int out_size)
{
    const float* unknown = (const float*)d_in[0];
    const float* known   = (const float*)d_in[1];
    const float* uf      = (const float*)d_in[2];
    const float* kf      = (const float*)d_in[3];
    const float* W1      = (const float*)d_in[4];
    const float* b1      = (const float*)d_in[5];
    const float* W2      = (const float*)d_in[6];
    const float* b2      = (const float*)d_in[7];
    float* out = (float*)d_out;

    float* p_kfT = nullptr;
    __half *p_B1 = nullptr, *p_B2 = nullptr, *p_W1s = nullptr, *p_W2s = nullptr;
    cudaGetSymbolAddress((void**)&p_kfT, g_kfT);
    cudaGetSymbolAddress((void**)&p_B1,  g_B1);
    cudaGetSymbolAddress((void**)&p_B2,  g_B2);
    cudaGetSymbolAddress((void**)&p_W1s, g_W1s);
    cudaGetSymbolAddress((void**)&p_W2s, g_W2s);

    cudaFuncSetAttribute(gemm_mma_kernel,
                         cudaFuncAttributeMaxDynamicSharedMemorySize, GSMEM);

    three_nn_kernel<<<dim3(NPTS / 256, BATCH), 256>>>(unknown, known);
    kf_transpose_kernel<<<dim3(MPTS / 32, C2 / 32, BATCH), 256>>>(kf, p_kfT);
    interp_fused_kernel<<<dim3(NPTS / 32, BATCH), 256>>>(p_kfT, uf, p_B1);

    convert_w_kernel<<<(256 * 384 + 256 * 256 + 255) / 256, 256>>>(W1, p_W1s, W2, p_W2s);

    // layer 1: Ksrc=384, epilogue writes B2 (fp16, transposed via smem)
    gemm_mma_kernel<<<dim3(NPTS / 128, 2, BATCH), 128, GSMEM>>>(
        p_W1s, b1, p_B1, nullptr, p_B2, 384);

    // layer 2: Ksrc=256, fp32 output
    gemm_mma_kernel<<<dim3(NPTS / 128, 2, BATCH), 128, GSMEM>>>(
        p_W2s, b2, p_B2, out, nullptr, 256);
}

// round 17
// speedup vs baseline: 1.0582x; 1.0582x over previous
#include <cuda_runtime.h>
#include <cuda_fp16.h>
#include <math.h>
#include <stdint.h>

#define BATCH 8
#define NPTS  8192
#define MPTS  2048
#define C1    128
#define C2    256
#define CMID  256

// ---------------- scratch (device globals; no allocation allowed) ----------
__device__ int   g_idx[BATCH * NPTS * 3];
__device__ float g_w  [BATCH * NPTS * 3];
__device__ __align__(256) __half g_kfT[BATCH * MPTS * C2];       // kf transposed fp16 [b][m][c]
__device__ __align__(256) __half g_B1 [BATCH * NPTS * 384];      // [b][n][384] fp16
__device__ __align__(256) __half g_B2 [BATCH * NPTS * 256];      // [b][n][256] fp16
__device__ __align__(256) __half g_W1s[256 * 384];               // [m][384] fp16
__device__ __align__(256) __half g_W2s[256 * 256];               // [m][256] fp16

// ---------------- helpers ----------------------------------------------------
__device__ __forceinline__ uint32_t smem_u32(const void* p) {
    uint32_t a;
    asm("{ .reg .u64 t; cvta.to.shared.u64 t, %1; cvt.u32.u64 %0, t; }" : "=r"(a) : "l"(p));
    return a;
}
#define CP_ASYNC16(dst, src) \
    asm volatile("cp.async.cg.shared.global [%0], [%1], 16;" :: "r"(dst), "l"(src))
#define CP_COMMIT() asm volatile("cp.async.commit_group;" ::: "memory")
#define CP_WAIT0()  asm volatile("cp.async.wait_group 0;" ::: "memory")
#define CP_WAIT1()  asm volatile("cp.async.wait_group 1;" ::: "memory")

#define LDSM4(r0, r1, r2, r3, addr) \
    asm volatile("ldmatrix.sync.aligned.m8n8.x4.shared.b16 {%0,%1,%2,%3}, [%4];" \
        : "=r"(r0), "=r"(r1), "=r"(r2), "=r"(r3) : "r"(addr))

#define MMAF16(d, a, b) \
    asm volatile("mma.sync.aligned.m16n8k16.row.col.f32.f16.f16.f32 " \
        "{%0,%1,%2,%3}, {%4,%5,%6,%7}, {%8,%9}, {%0,%1,%2,%3};" \
        : "+f"(d[0]), "+f"(d[1]), "+f"(d[2]), "+f"(d[3]) \
        : "r"(a[0]), "r"(a[1]), "r"(a[2]), "r"(a[3]), "r"(b[0]), "r"(b[1]))

__device__ __forceinline__ uint32_t pack_h2(float a, float b) {
    __half2 h = __floats2half2_rn(a, b);
    return *(uint32_t*)&h;
}

// ---------------- kernel 1: three_nn (1 pt/thread, t-space) ------------------
__global__ __launch_bounds__(256)
void three_nn_kernel(const float* __restrict__ unknown,
                     const float* __restrict__ known)
{
    __shared__ float4 sk[MPTS];
    const int b = blockIdx.y;
    const int j = blockIdx.x * blockDim.x + threadIdx.x;

    const float* kb = known + (size_t)b * MPTS * 3;
    for (int i = threadIdx.x; i < MPTS; i += blockDim.x) {
        float x = kb[i * 3 + 0], y = kb[i * 3 + 1], z = kb[i * 3 + 2];
        sk[i] = make_float4(x, y, z, x * x + y * y + z * z);
    }
    __syncthreads();

    const float* up = unknown + ((size_t)b * NPTS + j) * 3;
    const float ux = up[0], uy = up[1], uz = up[2];
    const float u2 = ux * ux + uy * uy + uz * uz;
    const float m2x = -2.0f * ux, m2y = -2.0f * uy, m2z = -2.0f * uz;

    float t0 = 3.4e38f, t1 = 3.4e38f, t2v = 3.4e38f;
    int i0 = 0, i1 = 0, i2 = 0;

    #pragma unroll 4
    for (int i = 0; i < MPTS; i++) {
        float4 k = sk[i];
        float t = fmaf(m2x, k.x, k.w);
        t = fmaf(m2y, k.y, t);
        t = fmaf(m2z, k.z, t);
        if (t < t2v) {
            if (t < t0)      { t2v = t1; i2 = i1; t1 = t0; i1 = i0; t0 = t; i0 = i; }
            else if (t < t1) { t2v = t1; i2 = i1; t1 = t;  i1 = i; }
            else             { t2v = t;  i2 = i; }
        }
    }

    float s0 = sqrtf(fmaxf(t0 + u2, 0.0f));
    float s1 = sqrtf(fmaxf(t1 + u2, 0.0f));
    float s2 = sqrtf(fmaxf(t2v + u2, 0.0f));
    float r0 = 1.0f / (s0 + 1e-8f);
    float r1 = 1.0f / (s1 + 1e-8f);
    float r2 = 1.0f / (s2 + 1e-8f);
    float rs = r0 + r1 + r2;

    const int o = ((b * NPTS) + j) * 3;
    g_idx[o + 0] = i0; g_idx[o + 1] = i1; g_idx[o + 2] = i2;
    g_w[o + 0] = r0 / rs; g_w[o + 1] = r1 / rs; g_w[o + 2] = r2 / rs;
}

// ---------------- kernel 2: transpose kf -> kfT fp16 [b][m][c] --------------
__global__ __launch_bounds__(256)
void kf_transpose_kernel(const float* __restrict__ kf, __half* __restrict__ kfT)
{
    __shared__ float s[32][33];
    const int b  = blockIdx.z;
    const int m0 = blockIdx.x * 32;
    const int c0 = blockIdx.y * 32;
    const int lane = threadIdx.x & 31, r = threadIdx.x >> 5;

    #pragma unroll
    for (int k = 0; k < 4; k++) {
        int c = r + k * 8;
        s[c][lane] = kf[((size_t)b * C2 + c0 + c) * MPTS + m0 + lane];
    }
    __syncthreads();
    #pragma unroll
    for (int k = 0; k < 4; k++) {
        int m = r + k * 8;
        kfT[((size_t)b * MPTS + m0 + m) * C2 + c0 + lane] = __float2half_rn(s[lane][m]);
    }
}

// ---------------- kernel 3: fused interp + uf -> B1 full rows (fp16) --------
// kfT is fp16: per point, each lane reads 8 channels = one uint4 per source row.
__global__ __launch_bounds__(256)
void interp_fused_kernel(const __half* __restrict__ kfT,
                         const float* __restrict__ uf,
                         __half* __restrict__ B1)
{
    __shared__ float s[C1][33];
    const int b    = blockIdx.y;
    const int j0   = blockIdx.x * 32;
    const int lane = threadIdx.x & 31;
    const int warp = threadIdx.x >> 5;

    #pragma unroll
    for (int k = 0; k < 16; k++) {
        int c = warp + k * 8;
        s[c][lane] = uf[((size_t)b * C1 + c) * NPTS + j0 + lane];
    }
    __syncthreads();

    const int jbase = j0 + warp * 4;
    #pragma unroll
    for (int t = 0; t < 4; t++) {
        const int j = jbase + t;
        const int o = ((b * NPTS) + j) * 3;
        const int   i0 = g_idx[o + 0], i1 = g_idx[o + 1], i2 = g_idx[o + 2];
        const float w0 = g_w[o + 0],   w1 = g_w[o + 1],   w2 = g_w[o + 2];

        uint4 A = *(const uint4*)(kfT + ((size_t)b * MPTS + i0) * C2 + lane * 8);
        uint4 B = *(const uint4*)(kfT + ((size_t)b * MPTS + i1) * C2 + lane * 8);
        uint4 C = *(const uint4*)(kfT + ((size_t)b * MPTS + i2) * C2 + lane * 8);

        const uint32_t* ap = (const uint32_t*)&A;
        const uint32_t* bp = (const uint32_t*)&B;
        const uint32_t* cp = (const uint32_t*)&C;

        uint4 hv;
        uint32_t* hp = (uint32_t*)&hv;
        #pragma unroll
        for (int q = 0; q < 4; q++) {
            float2 fa = __half22float2(*(const __half2*)&ap[q]);
            float2 fb = __half22float2(*(const __half2*)&bp[q]);
            float2 fc = __half22float2(*(const __half2*)&cp[q]);
            float vx = fa.x * w0 + fb.x * w1 + fc.x * w2;
            float vy = fa.y * w0 + fb.y * w1 + fc.y * w2;
            hp[q] = pack_h2(vx, vy);
        }

        *(uint4*)(B1 + ((size_t)b * NPTS + j) * 384 + lane * 8) = hv;
    }

    #pragma unroll
    for (int t = 0; t < 4; t++) {
        int jl = warp * 4 + t;
        __half* row = B1 + ((size_t)b * NPTS + j0 + jl) * 384 + 256;
        int c = lane * 4;
        uint2 out;
        out.x = pack_h2(s[c + 0][jl], s[c + 1][jl]);
        out.y = pack_h2(s[c + 2][jl], s[c + 3][jl]);
        *(uint2*)(row + c) = out;
    }
}

// ---------------- weight convert (both layers, one launch, plain fp16) ------
__global__ __launch_bounds__(256)
void convert_w_kernel(const float* __restrict__ W1, __half* __restrict__ W1s,
                      const float* __restrict__ W2, __half* __restrict__ W2s)
{
    int idx = blockIdx.x * 256 + threadIdx.x;
    const int N1 = 256 * 384;
    if (idx < N1) {
        W1s[idx] = __float2half_rn(W1[idx]);
    } else {
        int i2 = idx - N1;
        if (i2 >= 256 * 256) return;
        W2s[i2] = __float2half_rn(W2[i2]);
    }
}

// ---------------- mma.sync GEMM (plain fp16) + fused epilogue ----------------
// Exact R15 config: K=64 per stage, 2-stage double buffer.
// A = Ws [256][K] fp16; B = [b][n][K] fp16.  C = A.B
// CTA 128x128, 4 warps (warp 64x64), 2 CTA/SM.
// smem row = 128B data + 16B pad, pitch 144 (ldmatrix conflict-free).
#define PT 144
#define TILE_T 18432          // 128*144
#define STAGEB 36864          // A + B per stage
#define GSMEM  (2 * STAGEB)   // 73728

__global__ __launch_bounds__(128, 2)
void gemm_mma_kernel(const __half* __restrict__ Ws,
                     const float* __restrict__ bias,
                     const __half* __restrict__ Bmat,
                     float* __restrict__ Cout,
                     __half* __restrict__ B2out,
                     int Ksrc)
{
    extern __shared__ __align__(16) char smem[];
    const uint32_t sb = smem_u32(smem);

    const int tid  = threadIdx.x;
    const int wid  = tid >> 5;
    const int lane = tid & 31;
    const int wr   = wid >> 1;          // 0..1 (m half)
    const int wc   = wid & 1;           // 0..1 (n half)

    const int S  = Ksrc >> 6;           // 64-k stages

    const int b     = blockIdx.z;
    const int mBase = blockIdx.y * 128;
    const int nBase = blockIdx.x * 128;

    const __half* Abase = Ws + (size_t)mBase * Ksrc;
    const __half* Bbase = Bmat + ((size_t)b * NPTS + nBase) * Ksrc;

    float acc[4][8][4];
    #pragma unroll
    for (int i = 0; i < 4; i++)
        #pragma unroll
        for (int j = 0; j < 8; j++)
            #pragma unroll
            for (int q = 0; q < 4; q++) acc[i][j][q] = 0.0f;

    // load maps: each operand 128 rows x 8 chunks(16B); 1024 chunks, 8/thread
    #define LOAD_STAGE(sidx, buf) do {                                            \
        const int _s = (sidx);                                                    \
        const uint32_t _ab = sb + (buf) * STAGEB;                                 \
        const uint32_t _bb = _ab + TILE_T;                                        \
        _Pragma("unroll")                                                         \
        for (int _k = 0; _k < 8; _k++) {                                          \
            int _id = tid + _k * 128;                                             \
            int _r = _id >> 3, _q = _id & 7;                                      \
            CP_ASYNC16(_ab + _r * PT + _q * 16,                                   \
                       Abase + (size_t)_r * Ksrc + _s * 64 + _q * 8);             \
            CP_ASYNC16(_bb + _r * PT + _q * 16,                                   \
                       Bbase + (size_t)_r * Ksrc + _s * 64 + _q * 8);             \
        }                                                                         \
    } while (0)

    LOAD_STAGE(0, 0); CP_COMMIT();

    for (int s = 0; s < S; s++) {
        if (s + 1 < S) {
            LOAD_STAGE(s + 1, (s + 1) & 1);
            CP_COMMIT();
            CP_WAIT1();
        } else {
            CP_WAIT0();
        }
        __syncthreads();

        const uint32_t aB = sb + (s & 1) * STAGEB;
        const uint32_t bB = aB + TILE_T;

        #pragma unroll
        for (int kk = 0; kk < 4; kk++) {
            uint32_t ah[4][4];
            #pragma unroll
            for (int i = 0; i < 4; i++) {
                int row = wr * 64 + i * 16 + (lane & 15);
                uint32_t addr = aB + row * PT + kk * 32 + (lane >> 4) * 16;
                LDSM4(ah[i][0], ah[i][1], ah[i][2], ah[i][3], addr);
            }
            #pragma unroll
            for (int jp = 0; jp < 4; jp++) {
                uint32_t bf[4];
                int row = wc * 64 + jp * 16 + (lane & 15);
                uint32_t addr = bB + row * PT + kk * 32 + (lane >> 4) * 16;
                LDSM4(bf[0], bf[1], bf[2], bf[3], addr);
                uint32_t b0[2] = { bf[0], bf[2] };
                uint32_t b1[2] = { bf[1], bf[3] };
                #pragma unroll
                for (int i = 0; i < 4; i++) {
                    MMAF16(acc[i][jp * 2 + 0], ah[i], b0);
                    MMAF16(acc[i][jp * 2 + 1], ah[i], b1);
                }
            }
        }
        __syncthreads();
    }

    if (B2out) {
        // staged transpose: B2 [n][256] fp16 single plane
        __half* sm = (__half*)smem;          // [128 n][136 m]
        #pragma unroll
        for (int i = 0; i < 4; i++) {
            const int ml0 = wr * 64 + i * 16 + (lane >> 2);
            const float bv0 = bias[mBase + ml0];
            const float bv1 = bias[mBase + ml0 + 8];
            #pragma unroll
            for (int jn = 0; jn < 8; jn++) {
                const int nl = wc * 64 + jn * 8 + (lane & 3) * 2;
                #pragma unroll
                for (int q = 0; q < 4; q++) {
                    const int ml = ml0 + ((q >= 2) ? 8 : 0);
                    const int nn = nl + (q & 1);
                    const float v = fmaxf(acc[i][jn][q] + ((q >= 2) ? bv1 : bv0), 0.0f);
                    sm[nn * 136 + ml] = __float2half_rn(v);
                }
            }
        }
        __syncthreads();
        const __half* src = sm + tid * 136;
        __half* dstrow = B2out + ((size_t)b * NPTS + nBase + tid) * 256 + mBase;
        #pragma unroll
        for (int q = 0; q < 16; q++)
            *(uint4*)(dstrow + q * 8) = *(const uint4*)(src + q * 8);
    } else {
        float* Cb = Cout + (size_t)b * 256 * NPTS;
        #pragma unroll
        for (int i = 0; i < 4; i++) {
            const int r0 = mBase + wr * 64 + i * 16 + (lane >> 2);
            const float bv0 = bias[r0];
            const float bv1 = bias[r0 + 8];
            float* cr0 = Cb + (size_t)r0 * NPTS;
            float* cr1 = Cb + (size_t)(r0 + 8) * NPTS;
            #pragma unroll
            for (int jn = 0; jn < 8; jn++) {
                const int col = nBase + wc * 64 + jn * 8 + (lane & 3) * 2;
                float2 v0, v1;
                v0.x = fmaxf(acc[i][jn][0] + bv0, 0.0f);
                v0.y = fmaxf(acc[i][jn][1] + bv0, 0.0f);
                v1.x = fmaxf(acc[i][jn][2] + bv1, 0.0f);
                v1.y = fmaxf(acc[i][jn][3] + bv1, 0.0f);
                *(float2*)&cr0[col] = v0;
                *(float2*)&cr1[col] = v1;
            }
        }
    }
}

// ---------------- launch -----------------------------------------------------
extern "C" void kernel_launch(void* const* d_in, const int* in_sizes, int n_in,
                              void* d_out, int out_size)
{
    const float* unknown = (const float*)d_in[0];
    const float* known   = (const float*)d_in[1];
    const float* uf      = (const float*)d_in[2];
    const float* kf      = (const float*)d_in[3];
    const float* W1      = (const float*)d_in[4];
    const float* b1      = (const float*)d_in[5];
    const float* W2      = (const float*)d_in[6];
    const float* b2      = (const float*)d_in[7];
    float* out = (float*)d_out;

    __half *p_kfT = nullptr, *p_B1 = nullptr, *p_B2 = nullptr,
           *p_W1s = nullptr, *p_W2s = nullptr;
    cudaGetSymbolAddress((void**)&p_kfT, g_kfT);
    cudaGetSymbolAddress((void**)&p_B1,  g_B1);
    cudaGetSymbolAddress((void**)&p_B2,  g_B2);
    cudaGetSymbolAddress((void**)&p_W1s, g_W1s);
    cudaGetSymbolAddress((void**)&p_W2s, g_W2s);

    cudaFuncSetAttribute(gemm_mma_kernel,
                         cudaFuncAttributeMaxDynamicSharedMemorySize, GSMEM);

    three_nn_kernel<<<dim3(NPTS / 256, BATCH), 256>>>(unknown, known);
    kf_transpose_kernel<<<dim3(MPTS / 32, C2 / 32, BATCH), 256>>>(kf, p_kfT);
    interp_fused_kernel<<<dim3(NPTS / 32, BATCH), 256>>>(p_kfT, uf, p_B1);

    convert_w_kernel<<<(256 * 384 + 256 * 256 + 255) / 256, 256>>>(W1, p_W1s, W2, p_W2s);

    // layer 1: Ksrc=384, epilogue writes B2 (fp16, transposed via smem)
    gemm_mma_kernel<<<dim3(NPTS / 128, 2, BATCH), 128, GSMEM>>>(
        p_W1s, b1, p_B1, nullptr, p_B2, 384);

    // layer 2: Ksrc=256, fp32 output
    gemm_mma_kernel<<<dim3(NPTS / 128, 2, BATCH), 128, GSMEM>>>(
        p_W2s, b2, p_B2, out, nullptr, 256);
}